// round 1
// baseline (speedup 1.0000x reference)
#include <cuda_runtime.h>

#define NPTS 16384
#define CDIM 64
#define ODIM 128
#define KNN  16

// ---------------- scratch (no allocation allowed) ----------------
__device__ float g_base[NPTS * ODIM];   // x @ (W1a - W1b) + b1
__device__ float g_Bv[NPTS * ODIM];     // x @ W1b
__device__ float g_sq[NPTS];            // |x|^2
__device__ int   g_idx[NPTS * KNN];     // knn indices
__device__ float g_W2T[ODIM * ODIM];    // W2 transposed

// =================================================================
// precompute: base, Bv, sq.  4 points per block, 128 threads (o=tid)
// =================================================================
__global__ void __launch_bounds__(128) precompute_kernel(
    const float* __restrict__ x, const float* __restrict__ W1,
    const float* __restrict__ b1)
{
    const int n0  = blockIdx.x * 4;
    const int tid = threadIdx.x;
    __shared__ float xs[4][64];

    #pragma unroll
    for (int r = 0; r < 2; r++) {
        int li = r * 128 + tid;
        xs[li >> 6][li & 63] = x[n0 * 64 + li];
    }
    __syncthreads();

    float a1[4] = {0.f, 0.f, 0.f, 0.f};
    float a2[4] = {0.f, 0.f, 0.f, 0.f};
    #pragma unroll 4
    for (int c = 0; c < 64; c++) {
        float wa = W1[c * 128 + tid];
        float wb = W1[(64 + c) * 128 + tid];
        float wd = wa - wb;
        #pragma unroll
        for (int nn = 0; nn < 4; nn++) {
            float xv = xs[nn][c];
            a1[nn] = fmaf(xv, wd, a1[nn]);
            a2[nn] = fmaf(xv, wb, a2[nn]);
        }
    }
    float bb = b1[tid];
    #pragma unroll
    for (int nn = 0; nn < 4; nn++) {
        g_base[(n0 + nn) * 128 + tid] = a1[nn] + bb;
        g_Bv[(n0 + nn) * 128 + tid]  = a2[nn];
    }

    // squared norms: warp w reduces row w
    int w = tid >> 5, lane = tid & 31;
    float v = xs[w][lane] * xs[w][lane] + xs[w][lane + 32] * xs[w][lane + 32];
    #pragma unroll
    for (int off = 16; off > 0; off >>= 1)
        v += __shfl_xor_sync(0xffffffffu, v, off);
    if (lane == 0) g_sq[n0 + w] = v;
}

// =================================================================
// W2 transpose (tiny)
// =================================================================
__global__ void __launch_bounds__(256) w2t_kernel(const float* __restrict__ W2)
{
    int gid = blockIdx.x * 256 + threadIdx.x;   // grid 64 -> 16384
    int p = gid >> 7, o = gid & 127;
    g_W2T[p * 128 + o] = W2[o * 128 + p];
}

// =================================================================
// kNN: 64 queries/block, 256 blocks.  Tiled fp32 GEMM (score =
// 0.5*|xj|^2 - xi.xj, via an appended constant row) + register top-16.
// =================================================================
#define DSTR 68                       // padded dist row stride (floats)
#define SM_XI 0                       // [65][64]  = 4160 floats
#define SM_XJ 4160                    // [33][64]  = 2112 floats
#define SM_DS 6272                    // [64][68]  = 4352 floats
#define SM_TOT 10624                  // 42496 bytes (< 48KB static)

#define TOPK_INSERT(valx, jjx) do {                                        \
    float _d = (valx); int _j = (jjx);                                     \
    if (_d < kd[15]) {                                                     \
        _Pragma("unroll")                                                  \
        for (int _m = 0; _m < 16; _m++) {                                  \
            if (_d < kd[_m]) {                                             \
                float _td = kd[_m]; kd[_m] = _d; _d = _td;                 \
                int   _tj = ki[_m]; ki[_m] = _j; _j = _tj;                 \
            }                                                              \
        }                                                                  \
    }                                                                      \
} while (0)

__global__ void __launch_bounds__(256, 2) knn_kernel(const float* __restrict__ x)
{
    __shared__ __align__(16) float sm[SM_TOT];
    float* xiT = sm + SM_XI;
    float* xjT = sm + SM_XJ;
    float* dst = sm + SM_DS;

    const int tid = threadIdx.x;
    const int q0  = blockIdx.x * 64;

    // ---- load query tile transposed: xiT[c][i], plus row 64 = -0.5 ----
    {
        const int il = tid & 63, cq = (tid >> 6) * 16;
        const float4* src = (const float4*)(x + (q0 + il) * 64 + cq);
        #pragma unroll
        for (int u4 = 0; u4 < 4; u4++) {
            float4 v = src[u4];
            xiT[(cq + u4 * 4 + 0) * 64 + il] = v.x;
            xiT[(cq + u4 * 4 + 1) * 64 + il] = v.y;
            xiT[(cq + u4 * 4 + 2) * 64 + il] = v.z;
            xiT[(cq + u4 * 4 + 3) * 64 + il] = v.w;
        }
        if (tid < 64) xiT[64 * 64 + tid] = -0.5f;
    }

    const int ty = tid >> 4, tx = tid & 15;     // compute mapping (4x4 block)
    const int qs = tid >> 2, sl = tid & 3;      // scan mapping (query, j-quarter)

    float kd[16]; int ki[16];
    #pragma unroll
    for (int m = 0; m < 16; m++) { kd[m] = 1e30f; ki[m] = 0; }

    __syncthreads();

    for (int tile = 0; tile < NPTS / 64; tile++) {
        const int j0 = tile * 64;
        float acc[4][4];
        #pragma unroll
        for (int r = 0; r < 4; r++)
            #pragma unroll
            for (int s = 0; s < 4; s++) acc[r][s] = 0.f;

        const int jl = tid & 63, cq = (tid >> 6) * 8;

        // ---- half 0: c = 0..31 ----
        {
            const float4* src = (const float4*)(x + (j0 + jl) * 64 + cq);
            #pragma unroll
            for (int u4 = 0; u4 < 2; u4++) {
                float4 v = src[u4];
                xjT[(cq + u4 * 4 + 0) * 64 + jl] = v.x;
                xjT[(cq + u4 * 4 + 1) * 64 + jl] = v.y;
                xjT[(cq + u4 * 4 + 2) * 64 + jl] = v.z;
                xjT[(cq + u4 * 4 + 3) * 64 + jl] = v.w;
            }
        }
        __syncthreads();
        #pragma unroll 4
        for (int c = 0; c < 32; c++) {
            float4 a = *(const float4*)&xiT[c * 64 + ty * 4];
            float4 b = *(const float4*)&xjT[c * 64 + tx * 4];
            float ar[4] = {a.x, a.y, a.z, a.w};
            float bs[4] = {b.x, b.y, b.z, b.w};
            #pragma unroll
            for (int r = 0; r < 4; r++)
                #pragma unroll
                for (int s = 0; s < 4; s++)
                    acc[r][s] = fmaf(ar[r], bs[s], acc[r][s]);
        }
        __syncthreads();

        // ---- half 1: c = 32..63, plus row 32 = |xj|^2 ----
        {
            const float4* src = (const float4*)(x + (j0 + jl) * 64 + 32 + cq);
            #pragma unroll
            for (int u4 = 0; u4 < 2; u4++) {
                float4 v = src[u4];
                xjT[(cq + u4 * 4 + 0) * 64 + jl] = v.x;
                xjT[(cq + u4 * 4 + 1) * 64 + jl] = v.y;
                xjT[(cq + u4 * 4 + 2) * 64 + jl] = v.z;
                xjT[(cq + u4 * 4 + 3) * 64 + jl] = v.w;
            }
            if (tid < 64) xjT[32 * 64 + tid] = g_sq[j0 + tid];
        }
        __syncthreads();
        #pragma unroll 4
        for (int c = 0; c < 32; c++) {
            float4 a = *(const float4*)&xiT[(32 + c) * 64 + ty * 4];
            float4 b = *(const float4*)&xjT[c * 64 + tx * 4];
            float ar[4] = {a.x, a.y, a.z, a.w};
            float bs[4] = {b.x, b.y, b.z, b.w};
            #pragma unroll
            for (int r = 0; r < 4; r++)
                #pragma unroll
                for (int s = 0; s < 4; s++)
                    acc[r][s] = fmaf(ar[r], bs[s], acc[r][s]);
        }
        {   // c = 64: the score row (xiT row 64 = -0.5, xjT row 32 = sq)
            float4 a = *(const float4*)&xiT[64 * 64 + ty * 4];
            float4 b = *(const float4*)&xjT[32 * 64 + tx * 4];
            float ar[4] = {a.x, a.y, a.z, a.w};
            float bs[4] = {b.x, b.y, b.z, b.w};
            #pragma unroll
            for (int r = 0; r < 4; r++)
                #pragma unroll
                for (int s = 0; s < 4; s++)
                    acc[r][s] = fmaf(ar[r], bs[s], acc[r][s]);
        }

        // acc = xi.xj - 0.5|xj|^2  -> smaller (-acc) == closer
        #pragma unroll
        for (int r = 0; r < 4; r++) {
            float4 v = make_float4(-acc[r][0], -acc[r][1], -acc[r][2], -acc[r][3]);
            *(float4*)&dst[(ty * 4 + r) * DSTR + tx * 4] = v;
        }
        __syncthreads();

        // ---- scan my quarter of my query's row, maintain top-16 ----
        #pragma unroll
        for (int m4 = 0; m4 < 4; m4++) {
            float4 v = *(const float4*)&dst[qs * DSTR + sl * 16 + m4 * 4];
            int jb = j0 + sl * 16 + m4 * 4;
            TOPK_INSERT(v.x, jb + 0);
            TOPK_INSERT(v.y, jb + 1);
            TOPK_INSERT(v.z, jb + 2);
            TOPK_INSERT(v.w, jb + 3);
        }
        __syncthreads();
    }

    // ---- merge 4 sorted 16-lists per query ----
    float* candd = sm;                    // 4096 floats (aliases xiT)
    int*   candi = (int*)(sm + 4352);     // 4096 ints   (aliases xjT/dst head)
    #pragma unroll
    for (int m = 0; m < 16; m++) {
        candd[tid * 16 + m] = kd[m];
        candi[tid * 16 + m] = ki[m];
    }
    __syncthreads();
    if (tid < 64) {
        int p[4] = {0, 0, 0, 0};
        const int ob = (q0 + tid) * 16;
        #pragma unroll
        for (int m = 0; m < 16; m++) {
            float best = 1e30f; int bs = 0;
            #pragma unroll
            for (int s = 0; s < 4; s++) {
                float v = (p[s] < 16) ? candd[(tid * 4 + s) * 16 + p[s]] : 1e30f;
                if (v < best) { best = v; bs = s; }
            }
            g_idx[ob + m] = candi[(tid * 4 + bs) * 16 + p[bs]];
            p[bs]++;
        }
    }
}

// =================================================================
// aggregate: s = mean_k relu(base + Bv[j_k]);  out = s @ W2 + b2
// one point per block, 128 threads
// =================================================================
__global__ void __launch_bounds__(128) aggregate_kernel(
    const float* __restrict__ b2, float* __restrict__ out)
{
    const int n   = blockIdx.x;
    const int tid = threadIdx.x;
    __shared__ float ss[128];
    __shared__ int sidx[16];

    if (tid < 16) sidx[tid] = g_idx[n * 16 + tid];
    __syncthreads();

    float bv  = g_base[n * 128 + tid];
    float acc = 0.f;
    #pragma unroll
    for (int k = 0; k < 16; k++) {
        float v = bv + g_Bv[sidx[k] * 128 + tid];
        acc += fmaxf(v, 0.f);
    }
    ss[tid] = acc * (1.0f / 16.0f);
    __syncthreads();

    float r = b2[tid];
    const float4* wr = (const float4*)&g_W2T[tid * 128];
    #pragma unroll
    for (int o4 = 0; o4 < 32; o4++) {
        float4 w  = wr[o4];
        float4 sv = *(const float4*)&ss[o4 * 4];
        r = fmaf(w.x, sv.x, r);
        r = fmaf(w.y, sv.y, r);
        r = fmaf(w.z, sv.z, r);
        r = fmaf(w.w, sv.w, r);
    }
    out[n * 128 + tid] = r;
}

// =================================================================
extern "C" void kernel_launch(void* const* d_in, const int* in_sizes, int n_in,
                              void* d_out, int out_size)
{
    const float* x  = (const float*)d_in[0];
    const float* W1 = (const float*)d_in[1];
    const float* b1 = (const float*)d_in[2];
    const float* W2 = (const float*)d_in[3];
    const float* b2 = (const float*)d_in[4];
    float* out = (float*)d_out;

    precompute_kernel<<<NPTS / 4, 128>>>(x, W1, b1);
    w2t_kernel<<<64, 256>>>(W2);
    knn_kernel<<<NPTS / 64, 256>>>(x);
    aggregate_kernel<<<NPTS, 128>>>(b2, out);
}